// round 15
// baseline (speedup 1.0000x reference)
#include <cuda_runtime.h>
#include <cstdint>

// Problem constants (fixed shapes for SoftAgg_8873402434226)
#define Bn 8
#define Nn 65536
#define Dn 512
#define Sn 512

// Scratch (sanctioned: __device__ globals)
__device__ float g_denom[Sn * Bn * Dn];
__device__ float g_ynum[Sn * Bn * Dn];
__device__ float g_hy[Sn * Bn * Dn];
__device__ int   g_seg[Nn];
__device__ int   g_is64;
__device__ float g_xt[(size_t)Bn * Nn * Dn];   // x, tf32, rows permuted by segment sort
__device__ float g_wgt[Dn * Dn];               // Wg tf32
__device__ float g_wft[Dn * Dn];               // Wf tf32
__device__ int   g_cnt[Sn];                    // histogram
__device__ int   g_cur[Sn];                    // scatter cursors
__device__ int   g_sn[Nn];                     // sorted n (permutation)
__device__ int   g_ss[Nn];                     // seg of sorted position

// ---------------------------------------------------------------------------
__device__ __forceinline__ float f2tf32(float f) {
    unsigned o;
    asm("cvt.rna.tf32.f32 %0, %1;" : "=r"(o) : "f"(f));
    return __uint_as_float(o);
}

__device__ __forceinline__ void mma_tf32(float* c, const unsigned* a, const unsigned* b) {
    asm volatile(
        "mma.sync.aligned.m16n8k8.row.col.f32.tf32.tf32.f32 "
        "{%0,%1,%2,%3}, {%4,%5,%6,%7}, {%8,%9}, {%0,%1,%2,%3};"
        : "+f"(c[0]), "+f"(c[1]), "+f"(c[2]), "+f"(c[3])
        : "r"(a[0]), "r"(a[1]), "r"(a[2]), "r"(a[3]), "r"(b[0]), "r"(b[1]));
}

#define CP_ASYNC16(dst, src) \
    asm volatile("cp.async.cg.shared.global [%0], [%1], 16;" :: "r"(dst), "l"(src))
#define CP_COMMIT() asm volatile("cp.async.commit_group;" ::: "memory")
#define CP_WAIT1()  asm volatile("cp.async.wait_group 1;" ::: "memory")

__device__ __forceinline__ uint32_t smem_u32(const void* p) {
    uint32_t a;
    asm("{ .reg .u64 t; cvta.to.shared.u64 t, %1; cvt.u32.u64 %0, t; }" : "=r"(a) : "l"(p));
    return a;
}

// ---------------------------------------------------------------------------
// Kernel A: detect ix dtype + zero histogram
// ---------------------------------------------------------------------------
__global__ void detect_k(const int* __restrict__ ixw) {
    if (threadIdx.x < Sn) g_cnt[threadIdx.x] = 0;
    if (threadIdx.x == 0) {
        int z = 1;
        for (int i = 1; i < 128; i += 2)
            if (ixw[i] != 0) { z = 0; break; }
        g_is64 = z;
    }
}

__global__ void cvt_k(const int* __restrict__ ixw) {
    const int n = blockIdx.x * blockDim.x + threadIdx.x;
    int v = g_is64 ? ixw[2 * n] : ixw[n];
    g_seg[n] = v & (Sn - 1);
}

__global__ void hist_k() {
    const int n = blockIdx.x * blockDim.x + threadIdx.x;
    atomicAdd(&g_cnt[g_seg[n]], 1);
}

// Exclusive scan over 512 counts (one block, Hillis-Steele)
__global__ void scan_k() {
    __shared__ int tmp[Sn];
    const int t = threadIdx.x;
    const int c = g_cnt[t];
    tmp[t] = c;
    __syncthreads();
    for (int off = 1; off < Sn; off <<= 1) {
        int v = (t >= off) ? tmp[t - off] : 0;
        __syncthreads();
        tmp[t] += v;
        __syncthreads();
    }
    g_cur[t] = tmp[t] - c;   // exclusive offset = scatter cursor
}

__global__ void scat_k() {
    const int n = blockIdx.x * blockDim.x + threadIdx.x;
    const int s = g_seg[n];
    const int pos = atomicAdd(&g_cur[s], 1);
    g_sn[pos] = n;
    g_ss[pos] = s;
}

// x -> tf32, rows permuted into sorted order (per b)
__global__ void xsort_k(const float4* __restrict__ x) {
    const size_t i = (size_t)blockIdx.x * 256 + threadIdx.x;  // float4 index
    const int d4 = (int)(i & 127);
    const int row = (int)(i >> 7);          // b*N + m (sorted m)
    const int m  = row & (Nn - 1);
    const int b  = row >> 16;
    const int n  = g_sn[m];
    float4 v = x[((size_t)((b << 16) + n) << 7) + d4];
    v.x = f2tf32(v.x); v.y = f2tf32(v.y); v.z = f2tf32(v.z); v.w = f2tf32(v.w);
    ((float4*)g_xt)[i] = v;
}

__global__ void wcvt_k(const float4* __restrict__ Wg, const float4* __restrict__ Wf) {
    int i = blockIdx.x * 256 + threadIdx.x;
    float4 g = Wg[i];
    g.x = f2tf32(g.x); g.y = f2tf32(g.y); g.z = f2tf32(g.z); g.w = f2tf32(g.w);
    ((float4*)g_wgt)[i] = g;
    float4 f = Wf[i];
    f.x = f2tf32(f.x); f.y = f2tf32(f.y); f.z = f2tf32(f.z); f.w = f2tf32(f.w);
    ((float4*)g_wft)[i] = f;
}

__global__ void zero_k() {
    int i = blockIdx.x * blockDim.x + threadIdx.x;
    float4 z = make_float4(0.f, 0.f, 0.f, 0.f);
    ((float4*)g_denom)[i] = z;
    ((float4*)g_ynum)[i]  = z;
}

// ---------------------------------------------------------------------------
// main_k: fused dual tf32 GEMM (mma.sync) over segment-sorted rows +
//   smem run-length segment reduction epilogue (few atomics).
// CTA tile 128m x 128e, 8 warps = 2(m) x 4(e). Grid (4 e-chunks, 512 tiles, 8 b).
// ---------------------------------------------------------------------------
#define KC 32
#define AKS 36
#define A_F (128 * AKS)
#define B_F (256 * AKS)
#define STAGE_F (A_F + B_F)             // 13824 floats = 55296 B
#define SMEM_TOTAL (2 * STAGE_F * 4)    // 110592 B (epilogue reuses this space)

__global__ __launch_bounds__(256, 1)
void main_k(const float* __restrict__ bfv, const float* __restrict__ bgv)
{
    extern __shared__ float sm[];
    __shared__ int seg_s[128];
    const uint32_t sb = smem_u32(sm);

    const int tid  = threadIdx.x;
    const int lane = tid & 31;
    const int wid  = tid >> 5;
    const int lr   = lane >> 2, lq = lane & 3;
    const int wm   = wid & 1;            // m half (64 rows)
    const int we   = wid >> 1;           // e quarter (32 cols)

    const int eb    = blockIdx.x * 128;          // e base
    const int tile0 = blockIdx.y * 128;          // sorted-row base
    const int b     = blockIdx.z;
    const int row0  = (b << 16) + tile0;         // row base in sorted g_xt

    if (tid < 128) seg_s[tid] = g_ss[tile0 + tid];

    const int ar = tid >> 3, ac = tid & 7;

    float cg[4][4][4], cf[4][4][4];
    #pragma unroll
    for (int mt = 0; mt < 4; mt++)
        #pragma unroll
        for (int nt = 0; nt < 4; nt++)
            #pragma unroll
            for (int r = 0; r < 4; r++) { cg[mt][nt][r] = 0.f; cf[mt][nt][r] = 0.f; }

    auto stage = [&](int kc, int bs) {
        const uint32_t base = sb + (uint32_t)bs * STAGE_F * 4;
        const float* asrc = g_xt + (size_t)(row0 + ar) * Dn + kc * KC + ac * 4;
        #pragma unroll
        for (int it = 0; it < 4; it++) {
            uint32_t dst = base + ((ar + it * 32) * AKS + ac * 4) * 4;
            CP_ASYNC16(dst, asrc + (size_t)(it * 32) * Dn);
        }
        #pragma unroll
        for (int it = 0; it < 8; it++) {
            int n = ar + it * 32;
            const float* src = (n < 128)
                ? g_wgt + (size_t)(eb + n) * Dn + kc * KC + ac * 4
                : g_wft + (size_t)(eb + n - 128) * Dn + kc * KC + ac * 4;
            uint32_t dst = base + (A_F + n * AKS + ac * 4) * 4;
            CP_ASYNC16(dst, src);
        }
    };

    stage(0, 0);
    CP_COMMIT();

    for (int kc = 0; kc < Dn / KC; kc++) {
        if (kc + 1 < Dn / KC) stage(kc + 1, (kc + 1) & 1);
        CP_COMMIT();
        CP_WAIT1();
        __syncthreads();

        const float* Ab = sm + (kc & 1) * STAGE_F;
        const float* Bb = Ab + A_F;

        #pragma unroll
        for (int k8 = 0; k8 < KC / 8; k8++) {
            const int k0 = k8 * 8;
            unsigned a[4][4];
            #pragma unroll
            for (int mt = 0; mt < 4; mt++) {
                const float* ap = Ab + (wm * 64 + mt * 16 + lr) * AKS + k0 + lq;
                a[mt][0] = __float_as_uint(ap[0]);
                a[mt][1] = __float_as_uint(ap[8 * AKS]);
                a[mt][2] = __float_as_uint(ap[4]);
                a[mt][3] = __float_as_uint(ap[8 * AKS + 4]);
            }
            unsigned bg_[4][2], bf_[4][2];
            #pragma unroll
            for (int nt = 0; nt < 4; nt++) {
                const float* gp = Bb + (we * 32 + nt * 8 + lr) * AKS + k0 + lq;
                bg_[nt][0] = __float_as_uint(gp[0]);
                bg_[nt][1] = __float_as_uint(gp[4]);
                const float* fp = gp + 128 * AKS;
                bf_[nt][0] = __float_as_uint(fp[0]);
                bf_[nt][1] = __float_as_uint(fp[4]);
            }
            #pragma unroll
            for (int mt = 0; mt < 4; mt++)
                #pragma unroll
                for (int nt = 0; nt < 4; nt++) {
                    mma_tf32(cg[mt][nt], a[mt], bg_[nt]);
                    mma_tf32(cf[mt][nt], a[mt], bf_[nt]);
                }
        }
        __syncthreads();
    }

    // ---- epilogue: exp + f*exp to smem, run-length segment reduce, few atomics
    float* ev_s = sm;                  // [128][65]
    float* fv_s = sm + 128 * 65;       // [128][65]

    #pragma unroll
    for (int half = 0; half < 2; half++) {
        if (half) __syncthreads();     // protect buffers from previous iteration reads
        if ((we >> 1) == half) {
            const int wel = we & 1;
            #pragma unroll
            for (int mt = 0; mt < 4; mt++) {
                #pragma unroll
                for (int h = 0; h < 2; h++) {
                    const int row = wm * 64 + mt * 16 + h * 8 + lr;
                    #pragma unroll
                    for (int nt = 0; nt < 4; nt++) {
                        #pragma unroll
                        for (int cc = 0; cc < 2; cc++) {
                            const int lcol = wel * 32 + nt * 8 + 2 * lq + cc;
                            const int gcol = eb + half * 64 + lcol;
                            float ev = __expf(cg[mt][nt][h * 2 + cc] + bgv[gcol]);
                            float fe = (cf[mt][nt][h * 2 + cc] + bfv[gcol]) * ev;
                            ev_s[row * 65 + lcol] = ev;
                            fv_s[row * 65 + lcol] = fe;
                        }
                    }
                }
            }
        }
        __syncthreads();

        // 256 threads = 2 matrices x 2 row-ranges x 64 cols
        {
            const int m2   = tid >> 7;
            const int rr   = (tid >> 6) & 1;
            const int lcol = tid & 63;
            const float* src = m2 ? fv_s : ev_s;
            float* dst = m2 ? g_ynum : g_denom;
            const int gcol = eb + half * 64 + lcol;
            int sprev = seg_s[rr * 64];
            float sum = 0.f;
            #pragma unroll 8
            for (int r = 0; r < 64; r++) {
                const int row = rr * 64 + r;
                const int s = seg_s[row];
                if (s != sprev) {
                    atomicAdd(&dst[(sprev * Bn + b) * Dn + gcol], sum);
                    sum = 0.f;
                    sprev = s;
                }
                sum += src[row * 65 + lcol];
            }
            atomicAdd(&dst[(sprev * Bn + b) * Dn + gcol], sum);
        }
    }
}

// ---------------------------------------------------------------------------
// div, hy (fp32 SIMT), gather — unchanged
// ---------------------------------------------------------------------------
__global__ void div_k() {
    int i = blockIdx.x * blockDim.x + threadIdx.x;
    float4 d = ((const float4*)g_denom)[i];
    float4 a = ((const float4*)g_ynum)[i];
    float4 r;
    r.x = (d.x > 0.f) ? a.x / d.x : 0.f;
    r.y = (d.y > 0.f) ? a.y / d.y : 0.f;
    r.z = (d.z > 0.f) ? a.z / d.z : 0.f;
    r.w = (d.w > 0.f) ? a.w / d.w : 0.f;
    ((float4*)g_ynum)[i] = r;
}

#define HASTR 132
#define HBSTR 68

__global__ __launch_bounds__(256, 2)
void hy_k(const float* __restrict__ Wh, const float* __restrict__ bh)
{
    __shared__ float As[16 * HASTR];
    __shared__ float Bh[16 * HBSTR];

    const int tid = threadIdx.x;
    const int ec  = blockIdx.x;
    const int rr0 = blockIdx.y * 128;
    const int e0  = ec * 64;

    const int tx = tid & 15, ty = tid >> 4;
    const int m0 = ty * 8;
    const int srow = tid & 127, sh = tid >> 7;
    const int we = tid >> 2, wc = tid & 3;

    float acc[8][4];
    #pragma unroll
    for (int i = 0; i < 8; i++)
        #pragma unroll
        for (int j = 0; j < 4; j++) acc[i][j] = 0.f;

    const float4* y4  = (const float4*)g_ynum;
    const float4* wh4 = (const float4*)Wh;

    for (int kc = 0; kc < Dn; kc += 16) {
        const int kq = kc >> 2;
        #pragma unroll
        for (int it = 0; it < 2; it++) {
            int cc = sh * 2 + it;
            float4 v = y4[(size_t)(rr0 + srow) * 128 + kq + cc];
            As[(cc * 4 + 0) * HASTR + srow] = v.x;
            As[(cc * 4 + 1) * HASTR + srow] = v.y;
            As[(cc * 4 + 2) * HASTR + srow] = v.z;
            As[(cc * 4 + 3) * HASTR + srow] = v.w;
        }
        {
            float4 hv = wh4[(size_t)(e0 + we) * 128 + kq + wc];
            Bh[(wc * 4 + 0) * HBSTR + we] = hv.x;
            Bh[(wc * 4 + 1) * HBSTR + we] = hv.y;
            Bh[(wc * 4 + 2) * HBSTR + we] = hv.z;
            Bh[(wc * 4 + 3) * HBSTR + we] = hv.w;
        }
        __syncthreads();

        #pragma unroll
        for (int k = 0; k < 16; k++) {
            float4 a0 = *(const float4*)(As + k * HASTR + m0);
            float4 a1 = *(const float4*)(As + k * HASTR + m0 + 4);
            float4 bv = *(const float4*)(Bh + k * HBSTR + tx * 4);
            float a[8] = {a0.x, a0.y, a0.z, a0.w, a1.x, a1.y, a1.z, a1.w};
            float hv[4] = {bv.x, bv.y, bv.z, bv.w};
            #pragma unroll
            for (int i = 0; i < 8; i++)
                #pragma unroll
                for (int j = 0; j < 4; j++)
                    acc[i][j] += a[i] * hv[j];
        }
        __syncthreads();
    }

    const int ecol = e0 + tx * 4;
    float4 bv;
    bv.x = bh[ecol]; bv.y = bh[ecol + 1]; bv.z = bh[ecol + 2]; bv.w = bh[ecol + 3];
    #pragma unroll
    for (int i = 0; i < 8; i++) {
        float4 v;
        v.x = acc[i][0] + bv.x;
        v.y = acc[i][1] + bv.y;
        v.z = acc[i][2] + bv.z;
        v.w = acc[i][3] + bv.w;
        *(float4*)(g_hy + (size_t)(rr0 + m0 + i) * Dn + ecol) = v;
    }
}

__global__ void gather_k(float4* __restrict__ out)
{
    const int idx = blockIdx.x * 256 + threadIdx.x;
    const int e4 = idx & 127;
    const int nb = idx >> 7;
    const int n  = nb & (Nn - 1);
    const int b  = nb >> 16;
    const int s  = g_seg[n];
    out[idx] = ((const float4*)g_hy)[((s * Bn + b) << 7) + e4];
}

// ---------------------------------------------------------------------------
extern "C" void kernel_launch(void* const* d_in, const int* in_sizes, int n_in,
                              void* d_out, int out_size)
{
    const float* x   = (const float*)d_in[0];
    const int*   ixw = (const int*)d_in[1];
    const float* Wf  = (const float*)d_in[2];
    const float* bf  = (const float*)d_in[3];
    const float* Wg  = (const float*)d_in[4];
    const float* bg  = (const float*)d_in[5];
    const float* Wh  = (const float*)d_in[6];
    const float* bh  = (const float*)d_in[7];

    cudaFuncSetAttribute(main_k, cudaFuncAttributeMaxDynamicSharedMemorySize, SMEM_TOTAL);

    // 0) seg ids + counting sort + tf32 pre-conversion (x in sorted layout)
    detect_k<<<1, 512>>>(ixw);
    cvt_k<<<Nn / 256, 256>>>(ixw);
    hist_k<<<Nn / 256, 256>>>();
    scan_k<<<1, 512>>>();
    scat_k<<<Nn / 256, 256>>>();
    xsort_k<<<(int)(((size_t)Bn * Nn * Dn / 4) / 256), 256>>>((const float4*)x);
    wcvt_k<<<(Dn * Dn / 4) / 256, 256>>>((const float4*)Wg, (const float4*)Wf);

    // 1) zero accumulators
    zero_k<<<(Sn * Bn * Dn / 4) / 256, 256>>>();

    // 2) fused dual tf32 GEMM over sorted rows + segment-reduced epilogue
    main_k<<<dim3(4, Nn / 128, Bn), 256, SMEM_TOTAL>>>(bf, bg);

    // 3) y = ynum/denom
    div_k<<<(Sn * Bn * Dn / 4) / 256, 256>>>();

    // 4) hy = y @ Wh^T + bh
    hy_k<<<dim3(8, (Sn * Bn) / 128), 256>>>(Wh, bh);

    // 5) out = gather(hy, seg)
    gather_k<<<(Bn * Nn * 128) / 256, 256>>>((float4*)d_out);

    (void)in_sizes; (void)n_in; (void)out_size;
}

// round 16
// speedup vs baseline: 1.6608x; 1.6608x over previous
#include <cuda_runtime.h>
#include <cuda_fp16.h>
#include <cstdint>

// Problem constants (fixed shapes for SoftAgg_8873402434226)
#define Bn 8
#define Nn 65536
#define Dn 512
#define Sn 512

// Scratch (sanctioned: __device__ globals)
__device__ float  g_denom[Sn * Bn * Dn];
__device__ float  g_ynum[Sn * Bn * Dn];
__device__ float  g_hy[Sn * Bn * Dn];
__device__ int    g_seg[Nn];
__device__ int    g_is64;
__device__ __align__(16) __half g_xh[(size_t)Bn * Nn * Dn];  // x in fp16 (0.5 GB)
__device__ __align__(16) __half g_wgh[Dn * Dn];              // Wg fp16
__device__ __align__(16) __half g_wfh[Dn * Dn];              // Wf fp16

// ---------------------------------------------------------------------------
__device__ __forceinline__ uint32_t smem_u32(const void* p) {
    uint32_t a;
    asm("{ .reg .u64 t; cvta.to.shared.u64 t, %1; cvt.u32.u64 %0, t; }" : "=r"(a) : "l"(p));
    return a;
}

__device__ __forceinline__ uint32_t pack_h2(float a, float b) {
    __half2 h = __floats2half2_rn(a, b);
    return *reinterpret_cast<uint32_t*>(&h);
}

__device__ __forceinline__ void mma_f16(float* c, const unsigned* a, const unsigned* b) {
    asm volatile(
        "mma.sync.aligned.m16n8k16.row.col.f32.f16.f16.f32 "
        "{%0,%1,%2,%3}, {%4,%5,%6,%7}, {%8,%9}, {%0,%1,%2,%3};"
        : "+f"(c[0]), "+f"(c[1]), "+f"(c[2]), "+f"(c[3])
        : "r"(a[0]), "r"(a[1]), "r"(a[2]), "r"(a[3]), "r"(b[0]), "r"(b[1]));
}

#define CP_ASYNC16(dst, src) \
    asm volatile("cp.async.cg.shared.global [%0], [%1], 16;" :: "r"(dst), "l"(src))
#define CP_COMMIT() asm volatile("cp.async.commit_group;" ::: "memory")
#define CP_WAIT1()  asm volatile("cp.async.wait_group 1;" ::: "memory")

// ---------------------------------------------------------------------------
// Kernel 0: detect ix dtype
// ---------------------------------------------------------------------------
__global__ void detect_k(const int* __restrict__ ixw) {
    if (threadIdx.x == 0 && blockIdx.x == 0) {
        int z = 1;
        for (int i = 1; i < 128; i += 2)
            if (ixw[i] != 0) { z = 0; break; }
        g_is64 = z;
    }
}

// ---------------------------------------------------------------------------
// Kernel 1: seg ids + zero accumulators (fused). Grid 256 x 256.
// ---------------------------------------------------------------------------
__global__ void segzero_k(const int* __restrict__ ixw) {
    const int gid = blockIdx.x * 256 + threadIdx.x;     // 0..65535
    int v = g_is64 ? ixw[2 * gid] : ixw[gid];
    g_seg[gid] = v & (Sn - 1);
    float4 z = make_float4(0.f, 0.f, 0.f, 0.f);
    #pragma unroll
    for (int i = 0; i < 8; i++) {
        ((float4*)g_denom)[gid * 8 + i] = z;
        ((float4*)g_ynum)[gid * 8 + i]  = z;
    }
}

// ---------------------------------------------------------------------------
// Kernel 2: x, Wg, Wf -> fp16 (fused). Grid XBLOCKS (x) + 256 (W).
// ---------------------------------------------------------------------------
#define XBLOCKS ((int)(((size_t)Bn * Nn * Dn / 4) / 256))   // 262144

__global__ void xwcvt_k(const float4* __restrict__ x,
                        const float4* __restrict__ Wg, const float4* __restrict__ Wf) {
    if (blockIdx.x < XBLOCKS) {
        const size_t gi = (size_t)blockIdx.x * 256 + threadIdx.x;
        float4 v = x[gi];
        uint2 o;
        o.x = pack_h2(v.x, v.y);
        o.y = pack_h2(v.z, v.w);
        ((uint2*)g_xh)[gi] = o;
    } else {
        const int i = (blockIdx.x - XBLOCKS) * 256 + threadIdx.x;   // < Dn*Dn/4
        float4 g = Wg[i];
        uint2 og; og.x = pack_h2(g.x, g.y); og.y = pack_h2(g.z, g.w);
        ((uint2*)g_wgh)[i] = og;
        float4 f = Wf[i];
        uint2 of; of.x = pack_h2(f.x, f.y); of.y = pack_h2(f.z, f.w);
        ((uint2*)g_wfh)[i] = of;
    }
}

// ---------------------------------------------------------------------------
// Kernel 3 (main): fused dual fp16 GEMM (mma.sync m16n8k16) + exp + atomics.
// CTA tile 128m x 128e, 8 warps = 2(m) x 4(e), warp 64m x 32e x {g,f}.
// Smem: A[m][k] fp16 stride 72, B[e][k] fp16 stride 72 (g rows 0..127, f 128..255).
// k-chunk 64 fp16, 2-stage cp.async pipeline. All fragment LDS bank-bijective.
// ---------------------------------------------------------------------------
#define KCH 64
#define AKSH 72                         // fp16 row stride (144 B)
#define A_H (128 * AKSH)                // 9216 halfs
#define B_H (256 * AKSH)                // 18432 halfs
#define STAGE_H (A_H + B_H)             // 27648 halfs = 55296 B
#define SMEM_TOTAL (2 * STAGE_H * 2)    // 110592 B

__global__ __launch_bounds__(256, 1)
void main_k(const float* __restrict__ bfv, const float* __restrict__ bgv)
{
    extern __shared__ __half smh[];
    const uint32_t sb = smem_u32(smh);

    const int tid  = threadIdx.x;
    const int lane = tid & 31;
    const int wid  = tid >> 5;
    const int lr   = lane >> 2, lq = lane & 3;
    const int wm   = wid & 1;            // m half (64 rows)
    const int we   = wid >> 1;           // e quarter (32 cols)

    const int eb    = blockIdx.x * 128;  // e base
    const int row0  = blockIdx.y * 128;  // flattened row (b*N + n)
    const int b     = row0 >> 16;
    const int nbase = row0 & (Nn - 1);

    const int ar = tid >> 3, ac = tid & 7;   // staging coords

    float cg[4][4][4], cf[4][4][4];
    #pragma unroll
    for (int mt = 0; mt < 4; mt++)
        #pragma unroll
        for (int nt = 0; nt < 4; nt++)
            #pragma unroll
            for (int r = 0; r < 4; r++) { cg[mt][nt][r] = 0.f; cf[mt][nt][r] = 0.f; }

    auto stage = [&](int kc, int bs) {
        const uint32_t base = sb + (uint32_t)bs * STAGE_H * 2;
        // A: 128 rows x 64 k fp16 (8 halfs = 16B per cp.async)
        const __half* asrc = g_xh + (size_t)(row0 + ar) * Dn + kc * KCH + ac * 8;
        #pragma unroll
        for (int it = 0; it < 4; it++) {
            uint32_t dst = base + ((ar + it * 32) * AKSH + ac * 8) * 2;
            CP_ASYNC16(dst, asrc + (size_t)(it * 32) * Dn);
        }
        // B: 256 rows (Wg then Wf) x 64 k
        #pragma unroll
        for (int it = 0; it < 8; it++) {
            int n = ar + it * 32;
            const __half* src = (n < 128)
                ? g_wgh + (size_t)(eb + n) * Dn + kc * KCH + ac * 8
                : g_wfh + (size_t)(eb + n - 128) * Dn + kc * KCH + ac * 8;
            uint32_t dst = base + (A_H + n * AKSH + ac * 8) * 2;
            CP_ASYNC16(dst, src);
        }
    };

    stage(0, 0);
    CP_COMMIT();

    for (int kc = 0; kc < Dn / KCH; kc++) {
        if (kc + 1 < Dn / KCH) stage(kc + 1, (kc + 1) & 1);
        CP_COMMIT();
        CP_WAIT1();
        __syncthreads();

        const __half* Ab = smh + (kc & 1) * STAGE_H;
        const __half* Bb = Ab + A_H;

        #pragma unroll
        for (int kk = 0; kk < KCH / 16; kk++) {
            const int k0 = kk * 16 + 2 * lq;
            unsigned a[4][4];
            #pragma unroll
            for (int mt = 0; mt < 4; mt++) {
                const __half* ap = Ab + (wm * 64 + mt * 16 + lr) * AKSH + k0;
                a[mt][0] = *(const uint32_t*)(ap);
                a[mt][1] = *(const uint32_t*)(ap + 8 * AKSH);
                a[mt][2] = *(const uint32_t*)(ap + 8);
                a[mt][3] = *(const uint32_t*)(ap + 8 * AKSH + 8);
            }
            unsigned bg_[4][2], bf_[4][2];
            #pragma unroll
            for (int nt = 0; nt < 4; nt++) {
                const __half* gp = Bb + (we * 32 + nt * 8 + lr) * AKSH + k0;
                bg_[nt][0] = *(const uint32_t*)(gp);
                bg_[nt][1] = *(const uint32_t*)(gp + 8);
                const __half* fp = gp + 128 * AKSH;
                bf_[nt][0] = *(const uint32_t*)(fp);
                bf_[nt][1] = *(const uint32_t*)(fp + 8);
            }
            #pragma unroll
            for (int mt = 0; mt < 4; mt++)
                #pragma unroll
                for (int nt = 0; nt < 4; nt++) {
                    mma_f16(cg[mt][nt], a[mt], bg_[nt]);
                    mma_f16(cf[mt][nt], a[mt], bf_[nt]);
                }
        }
        __syncthreads();
    }

    // epilogue: bias, exp, atomic scatter (R12-proven; atomics overlap MMA waves)
    float biasg[4][2], biasf[4][2];
    #pragma unroll
    for (int nt = 0; nt < 4; nt++)
        #pragma unroll
        for (int cc = 0; cc < 2; cc++) {
            const int col = eb + we * 32 + nt * 8 + 2 * lq + cc;
            biasg[nt][cc] = bgv[col];
            biasf[nt][cc] = bfv[col];
        }

    #pragma unroll
    for (int mt = 0; mt < 4; mt++) {
        #pragma unroll
        for (int h = 0; h < 2; h++) {
            const int seg = g_seg[nbase + wm * 64 + mt * 16 + h * 8 + lr];
            const int base = ((seg * Bn + b) << 9) + eb + we * 32 + 2 * lq;
            #pragma unroll
            for (int nt = 0; nt < 4; nt++) {
                #pragma unroll
                for (int cc = 0; cc < 2; cc++) {
                    const int o = base + nt * 8 + cc;
                    float ev = __expf(cg[mt][nt][h * 2 + cc] + biasg[nt][cc]);
                    atomicAdd(&g_denom[o], ev);
                    atomicAdd(&g_ynum[o], (cf[mt][nt][h * 2 + cc] + biasf[nt][cc]) * ev);
                }
            }
        }
    }
}

// ---------------------------------------------------------------------------
// div, hy (fp32 SIMT), gather — unchanged from R12
// ---------------------------------------------------------------------------
__global__ void div_k() {
    int i = blockIdx.x * blockDim.x + threadIdx.x;
    float4 d = ((const float4*)g_denom)[i];
    float4 a = ((const float4*)g_ynum)[i];
    float4 r;
    r.x = (d.x > 0.f) ? a.x / d.x : 0.f;
    r.y = (d.y > 0.f) ? a.y / d.y : 0.f;
    r.z = (d.z > 0.f) ? a.z / d.z : 0.f;
    r.w = (d.w > 0.f) ? a.w / d.w : 0.f;
    ((float4*)g_ynum)[i] = r;
}

#define HASTR 132
#define HBSTR 68

__global__ __launch_bounds__(256, 2)
void hy_k(const float* __restrict__ Wh, const float* __restrict__ bh)
{
    __shared__ float As[16 * HASTR];
    __shared__ float Bh[16 * HBSTR];

    const int tid = threadIdx.x;
    const int ec  = blockIdx.x;
    const int rr0 = blockIdx.y * 128;
    const int e0  = ec * 64;

    const int tx = tid & 15, ty = tid >> 4;
    const int m0 = ty * 8;
    const int srow = tid & 127, sh = tid >> 7;
    const int we = tid >> 2, wc = tid & 3;

    float acc[8][4];
    #pragma unroll
    for (int i = 0; i < 8; i++)
        #pragma unroll
        for (int j = 0; j < 4; j++) acc[i][j] = 0.f;

    const float4* y4  = (const float4*)g_ynum;
    const float4* wh4 = (const float4*)Wh;

    for (int kc = 0; kc < Dn; kc += 16) {
        const int kq = kc >> 2;
        #pragma unroll
        for (int it = 0; it < 2; it++) {
            int cc = sh * 2 + it;
            float4 v = y4[(size_t)(rr0 + srow) * 128 + kq + cc];
            As[(cc * 4 + 0) * HASTR + srow] = v.x;
            As[(cc * 4 + 1) * HASTR + srow] = v.y;
            As[(cc * 4 + 2) * HASTR + srow] = v.z;
            As[(cc * 4 + 3) * HASTR + srow] = v.w;
        }
        {
            float4 hv = wh4[(size_t)(e0 + we) * 128 + kq + wc];
            Bh[(wc * 4 + 0) * HBSTR + we] = hv.x;
            Bh[(wc * 4 + 1) * HBSTR + we] = hv.y;
            Bh[(wc * 4 + 2) * HBSTR + we] = hv.z;
            Bh[(wc * 4 + 3) * HBSTR + we] = hv.w;
        }
        __syncthreads();

        #pragma unroll
        for (int k = 0; k < 16; k++) {
            float4 a0 = *(const float4*)(As + k * HASTR + m0);
            float4 a1 = *(const float4*)(As + k * HASTR + m0 + 4);
            float4 bv = *(const float4*)(Bh + k * HBSTR + tx * 4);
            float a[8] = {a0.x, a0.y, a0.z, a0.w, a1.x, a1.y, a1.z, a1.w};
            float hv[4] = {bv.x, bv.y, bv.z, bv.w};
            #pragma unroll
            for (int i = 0; i < 8; i++)
                #pragma unroll
                for (int j = 0; j < 4; j++)
                    acc[i][j] += a[i] * hv[j];
        }
        __syncthreads();
    }

    const int ecol = e0 + tx * 4;
    float4 bv;
    bv.x = bh[ecol]; bv.y = bh[ecol + 1]; bv.z = bh[ecol + 2]; bv.w = bh[ecol + 3];
    #pragma unroll
    for (int i = 0; i < 8; i++) {
        float4 v;
        v.x = acc[i][0] + bv.x;
        v.y = acc[i][1] + bv.y;
        v.z = acc[i][2] + bv.z;
        v.w = acc[i][3] + bv.w;
        *(float4*)(g_hy + (size_t)(rr0 + m0 + i) * Dn + ecol) = v;
    }
}

__global__ void gather_k(float4* __restrict__ out)
{
    const int idx = blockIdx.x * 256 + threadIdx.x;
    const int e4 = idx & 127;
    const int nb = idx >> 7;
    const int n  = nb & (Nn - 1);
    const int b  = nb >> 16;
    const int s  = g_seg[n];
    out[idx] = ((const float4*)g_hy)[((s * Bn + b) << 7) + e4];
}

// ---------------------------------------------------------------------------
extern "C" void kernel_launch(void* const* d_in, const int* in_sizes, int n_in,
                              void* d_out, int out_size)
{
    const float* x   = (const float*)d_in[0];
    const int*   ixw = (const int*)d_in[1];
    const float* Wf  = (const float*)d_in[2];
    const float* bf  = (const float*)d_in[3];
    const float* Wg  = (const float*)d_in[4];
    const float* bg  = (const float*)d_in[5];
    const float* Wh  = (const float*)d_in[6];
    const float* bh  = (const float*)d_in[7];

    cudaFuncSetAttribute(main_k, cudaFuncAttributeMaxDynamicSharedMemorySize, SMEM_TOTAL);

    // (0) detect dtype  (1) seg ids + zero accumulators  (2) x/W -> fp16
    detect_k<<<1, 32>>>(ixw);
    segzero_k<<<Nn / 256, 256>>>(ixw);
    xwcvt_k<<<XBLOCKS + (Dn * Dn / 4) / 256, 256>>>(
        (const float4*)x, (const float4*)Wg, (const float4*)Wf);

    // (3) fused dual fp16 GEMM + exp + segment atomic accumulation
    main_k<<<dim3(4, (Bn * Nn) / 128), 256, SMEM_TOTAL>>>(bf, bg);

    // (4) y = ynum/denom   (5) hy = y @ Wh^T + bh   (6) gather
    div_k<<<(Sn * Bn * Dn / 4) / 256, 256>>>();
    hy_k<<<dim3(8, (Sn * Bn) / 128), 256>>>(Wh, bh);
    gather_k<<<(Bn * Nn * 128) / 256, 256>>>((float4*)d_out);

    (void)in_sizes; (void)n_in; (void)out_size;
}